// round 12
// baseline (speedup 1.0000x reference)
#include <cuda_runtime.h>
#include <cuda_fp16.h>
#include <math.h>

// ---------------- problem constants ----------------
#define MAX_NODES 50000
#define MAX_EDGES 800000

// fp16-compressed per-node records (channel order): per lane 12 halves = uint4 + uint2 (24B)
__device__ uint4 g_node4[MAX_NODES * 32];
__device__ uint2 g_node2[MAX_NODES * 32];

// CSR-by-dst scratch
__device__ int g_cnt[MAX_NODES];
__device__ int g_off[MAX_NODES + 1];
__device__ int g_pos[MAX_NODES];
__device__ int g_perm[MAX_EDGES];

// ---- constants derived from the reference's (non-standard) CG formula ----
#define ALPHA0 0.125f
#define ALPHA1 0.10206207261596575f
#define D0 0.6666666666666666f
#define D1 0.3333333333333333f
#define E0 0.6963106238227914f
#define E1 0.17407765595569785f
#define N1 0.48888007f
#define N2 0.04704256f
#define N3 0.06111001f
#define N4 0.12222002f

#define NPW 4   // nodes per warp in precompute

static __device__ __forceinline__ unsigned pack2(float a, float b) {
    half2 h = __floats2half2_rn(a, b);
    return *reinterpret_cast<unsigned*>(&h);
}
static __device__ __forceinline__ float2 unpack2(unsigned u) {
    half2 h = *reinterpret_cast<half2*>(&u);
    return __half22float2(h);
}

// ---------------- counting sort of edges by dst ----------------
__global__ void hist_kernel(const int* __restrict__ eidx, int n_edges) {
    int e = blockIdx.x * blockDim.x + threadIdx.x;
    if (e < n_edges) atomicAdd(&g_cnt[eidx[n_edges + e]], 1);
}

__global__ void scan_kernel(int n_nodes) {   // single block, 1024 threads
    __shared__ int ssum[1024];
    int t = threadIdx.x;
    const int SEG = (MAX_NODES + 1023) / 1024;
    int base = t * SEG;
    int s = 0;
    for (int i = 0; i < SEG; i++) {
        int idx = base + i;
        if (idx < n_nodes) s += g_cnt[idx];
    }
    ssum[t] = s;
    __syncthreads();
    for (int d = 1; d < 1024; d <<= 1) {
        int v = (t >= d) ? ssum[t - d] : 0;
        __syncthreads();
        ssum[t] += v;
        __syncthreads();
    }
    int run = (t == 0) ? 0 : ssum[t - 1];
    for (int i = 0; i < SEG; i++) {
        int idx = base + i;
        if (idx < n_nodes) {
            g_off[idx] = run;
            g_pos[idx] = run;
            run += g_cnt[idx];
        }
    }
    if (t == 1023) g_off[n_nodes] = ssum[1023];
}

__global__ void scatter_kernel(const int* __restrict__ eidx, int n_edges) {
    int e = blockIdx.x * blockDim.x + threadIdx.x;
    if (e < n_edges) {
        int p = atomicAdd(&g_pos[eidx[n_edges + e]], 1);
        g_perm[p] = e;
    }
}

// ---------------- per-node precompute: 4 nodes/warp, lane = channel ----------------
__global__ void __launch_bounds__(256) precompute_kernel(const float* __restrict__ feat,
                                                         const float* __restrict__ W,
                                                         int n_nodes) {
    __shared__ float Ws[5 * 1024];
    __shared__ float4 xs[8][NPW * 32];

    for (int i = threadIdx.x; i < 5 * 1024; i += blockDim.x) {
        int p = i >> 10;
        float s = (p == 0 || p == 3) ? ALPHA0 : ALPHA1;
        Ws[i] = s * W[i];
    }
    __syncthreads();

    int lane = threadIdx.x & 31;
    int wl   = threadIdx.x >> 5;
    int warp = (blockIdx.x * blockDim.x + threadIdx.x) >> 5;
    int nwarp = (gridDim.x * blockDim.x) >> 5;

    for (int nb = warp * NPW; nb < n_nodes; nb += nwarp * NPW) {
        #pragma unroll
        for (int nn = 0; nn < NPW; nn++) {
            int n = nb + nn;
            float4 v = make_float4(0.f, 0.f, 0.f, 0.f);
            if (n < n_nodes) {
                const float* x = feat + (size_t)n * 128;
                v.x = x[lane];
                v.y = x[32 + 3 * lane];
                v.z = x[33 + 3 * lane];
                v.w = x[34 + 3 * lane];
            }
            xs[wl][nn * 32 + lane] = v;
        }
        __syncwarp();

        float a1[NPW], a2[NPW], b3[NPW][3], b4[NPW][3], b5[NPW][3];
        #pragma unroll
        for (int nn = 0; nn < NPW; nn++) {
            a1[nn] = 0.f; a2[nn] = 0.f;
            #pragma unroll
            for (int k = 0; k < 3; k++) { b3[nn][k] = 0.f; b4[nn][k] = 0.f; b5[nn][k] = 0.f; }
        }

        #pragma unroll 4
        for (int u = 0; u < 32; u++) {
            float w0 = Ws[          u * 32 + lane];
            float w1 = Ws[1024 +    u * 32 + lane];
            float w2 = Ws[2048 +    u * 32 + lane];
            float w3 = Ws[3072 +    u * 32 + lane];
            float w4 = Ws[4096 +    u * 32 + lane];
            #pragma unroll
            for (int nn = 0; nn < NPW; nn++) {
                float4 v = xs[wl][nn * 32 + u];   // broadcast
                a1[nn] = fmaf(v.x, w0, a1[nn]);
                a2[nn] = fmaf(v.x, w1, a2[nn]);
                b3[nn][0] = fmaf(v.y, w2, b3[nn][0]);
                b3[nn][1] = fmaf(v.z, w2, b3[nn][1]);
                b3[nn][2] = fmaf(v.w, w2, b3[nn][2]);
                b4[nn][0] = fmaf(v.y, w3, b4[nn][0]);
                b4[nn][1] = fmaf(v.z, w3, b4[nn][1]);
                b4[nn][2] = fmaf(v.w, w3, b4[nn][2]);
                b5[nn][0] = fmaf(v.y, w4, b5[nn][0]);
                b5[nn][1] = fmaf(v.z, w4, b5[nn][1]);
                b5[nn][2] = fmaf(v.w, w4, b5[nn][2]);
            }
        }

        #pragma unroll
        for (int nn = 0; nn < NPW; nn++) {
            int n = nb + nn;
            if (n >= n_nodes) break;
            float c30 = b3[nn][0] * D0, c31 = b3[nn][1] * D1, c32 = b3[nn][2] * D0;
            float c40 = b4[nn][0] * E0, c41 = b4[nn][1] * E1, c42 = b4[nn][2] * E0;
            uint4 p;
            p.x = pack2(a1[nn], a2[nn]);
            p.y = pack2(c30, c31);
            p.z = pack2(c32, c40);
            p.w = pack2(c41, c42);
            uint2 q;
            q.x = pack2(b5[nn][0], b5[nn][1]);
            q.y = pack2(b5[nn][2], 0.f);
            g_node4[n * 32 + lane] = p;
            g_node2[n * 32 + lane] = q;
        }
        __syncwarp();
    }
}

// ---------------- pull kernel: warp per dst node, register accumulation, single store ----------------
__global__ void __launch_bounds__(256) edge_pull_kernel(const float* __restrict__ sh,
                                                        const int* __restrict__ eidx,
                                                        float* __restrict__ out,
                                                        int n_edges, int n_nodes) {
    __shared__ __align__(16) float buf[8][128];
    const unsigned FULL = 0xFFFFFFFFu;
    int lane  = threadIdx.x & 31;
    int wl    = threadIdx.x >> 5;
    int warp  = (blockIdx.x * blockDim.x + threadIdx.x) >> 5;
    int nwarp = (gridDim.x * blockDim.x) >> 5;
    float* b = buf[wl];

    for (int node = warp; node < n_nodes; node += nwarp) {
        int beg = g_off[node], end = g_off[node + 1];

        float acc0 = 0.f, acc1x = 0.f, acc1y = 0.f, acc1z = 0.f;

        for (int base = beg; base < end; base += 32) {
            int m = min(32, end - base);
            // chunk: lane-parallel load of edge ids and src nodes
            int e_l = 0, src_l = 0;
            if (lane < m) {
                e_l   = g_perm[base + lane];
                src_l = eidx[e_l];
            }
            // prime: sh for edge 0 of chunk
            int e0 = __shfl_sync(FULL, e_l, 0);
            float sv = (lane < 9) ? sh[(size_t)e0 * 9 + lane] : 0.f;

            for (int j = 0; j < m; j++) {
                // issue record gather for current edge first (longest latency)
                int srcj = __shfl_sync(FULL, src_l, j);
                uint4 rp = g_node4[srcj * 32 + lane];
                uint2 rq = g_node2[srcj * 32 + lane];

                // prefetch next edge's sh while the gather is in flight
                float nsv = 0.f;
                if (j + 1 < m) {
                    int e1 = __shfl_sync(FULL, e_l, j + 1);
                    nsv = (lane < 9) ? sh[(size_t)e1 * 9 + lane] : 0.f;
                }

                // broadcast sh components
                float s0  = __shfl_sync(FULL, sv, 0);
                float s1x = __shfl_sync(FULL, sv, 1);
                float s1y = __shfl_sync(FULL, sv, 2);
                float s1z = __shfl_sync(FULL, sv, 3);
                float q0  = __shfl_sync(FULL, sv, 4);
                float q1v = __shfl_sync(FULL, sv, 5);
                float q2  = __shfl_sync(FULL, sv, 6);
                float q3  = __shfl_sync(FULL, sv, 7);
                float q4  = __shfl_sync(FULL, sv, 8);

                float n2q2 = N2 * q2;
                float n1q4 = N1 * q4;
                float n1q0 = N1 * q0;
                float n3q1 = N3 * q1v;
                float n4q1 = N4 * q1v;
                float n3q3 = N3 * q3;
                float n4q3 = N4 * q3;

                float2 u0 = unpack2(rp.x);   // a1, a2
                float2 u1 = unpack2(rp.y);   // b3x, b3y
                float2 u2 = unpack2(rp.z);   // b3z, b4x
                float2 u3 = unpack2(rp.w);   // b4y, b4z
                float2 u4 = unpack2(rq.x);   // b5x, b5y
                float2 u5 = unpack2(rq.y);   // b5z, -
                float a1 = u0.x, a2 = u0.y;
                float b3x = u1.x, b3y = u1.y, b3z = u2.x;
                float b4x = u2.y, b4y = u3.x, b4z = u3.y;
                float b5x = u4.x, b5y = u4.y, b5z = u5.x;

                // out0: paths (0,0,0) and (1,1,0)
                acc0 = fmaf(s0, a1, acc0);
                acc0 = fmaf(s1x, b4x, acc0);
                acc0 = fmaf(s1y, b4y, acc0);
                acc0 = fmaf(s1z, b4z, acc0);

                // out1: paths (0,1,1), (1,0,1), (1,2,1)
                acc1x = fmaf(D0 * s1x, a2,
                        fmaf(s0, b3x,
                        fmaf(-(n2q2 + n1q4), b5x,
                        fmaf(n3q1, b5y, fmaf(n1q0, b5z, acc1x)))));
                acc1y = fmaf(D1 * s1y, a2,
                        fmaf(s0, b3y,
                        fmaf(n4q1, b5x,
                        fmaf(n2q2, b5y, fmaf(n4q3, b5z, acc1y)))));
                acc1z = fmaf(D0 * s1z, a2,
                        fmaf(s0, b3z,
                        fmaf(n1q0, b5x,
                        fmaf(n3q3, b5y, fmaf((n1q4 - n2q2), b5z, acc1z)))));

                sv = nsv;
            }
        }

        // transpose once per node via SMEM, then plain vector store (exclusive owner)
        b[lane]              = acc0;
        b[32 + 3 * lane + 0] = acc1x;
        b[32 + 3 * lane + 1] = acc1y;
        b[32 + 3 * lane + 2] = acc1z;
        __syncwarp();
        float4 v4 = *reinterpret_cast<float4*>(b + 4 * lane);
        *reinterpret_cast<float4*>(out + (size_t)node * 128 + 4 * lane) = v4;
        __syncwarp();
    }
}

// ---------------- launch ----------------
extern "C" void kernel_launch(void* const* d_in, const int* in_sizes, int n_in,
                              void* d_out, int out_size) {
    const float* feat = (const float*)d_in[0];
    const float* sh   = (const float*)d_in[1];
    const int*   eidx = (const int*)d_in[2];
    const float* W    = (const float*)d_in[3];
    int n_nodes = in_sizes[0] / 128;
    int n_edges = in_sizes[2] / 2;

    void* cnt_ptr = nullptr;
    cudaGetSymbolAddress(&cnt_ptr, g_cnt);
    cudaMemsetAsync(cnt_ptr, 0, (size_t)n_nodes * sizeof(int));

    int eb = (n_edges + 255) / 256;
    hist_kernel<<<eb, 256>>>(eidx, n_edges);
    scan_kernel<<<1, 1024>>>(n_nodes);
    scatter_kernel<<<eb, 256>>>(eidx, n_edges);

    int warps_needed = (n_nodes + NPW - 1) / NPW;
    int pre_blocks = (warps_needed + 7) / 8;
    precompute_kernel<<<pre_blocks, 256>>>(feat, W, n_nodes);

    int nb = (n_nodes + 7) / 8;   // warp per node, 8 warps per block
    edge_pull_kernel<<<nb, 256>>>(sh, eidx, (float*)d_out, n_edges, n_nodes);
}

// round 13
// speedup vs baseline: 1.6227x; 1.6227x over previous
#include <cuda_runtime.h>
#include <cuda_fp16.h>
#include <math.h>

// ---------------- problem constants ----------------
#define MAX_NODES 50000

// fp16-compressed per-node records (channel order): per lane 12 halves = uint4 + uint2 (24B)
__device__ uint4 g_node4[MAX_NODES * 32];
__device__ uint2 g_node2[MAX_NODES * 32];

// ---- constants derived from the reference's (non-standard) CG formula ----
#define ALPHA0 0.125f
#define ALPHA1 0.10206207261596575f
#define D0 0.6666666666666666f
#define D1 0.3333333333333333f
#define E0 0.6963106238227914f
#define E1 0.17407765595569785f
#define N1 0.48888007f
#define N2 0.04704256f
#define N3 0.06111001f
#define N4 0.12222002f

#define NPW 4   // nodes per warp in precompute

static __device__ __forceinline__ unsigned pack2(float a, float b) {
    half2 h = __floats2half2_rn(a, b);
    return *reinterpret_cast<unsigned*>(&h);
}
static __device__ __forceinline__ float2 unpack2(unsigned u) {
    half2 h = *reinterpret_cast<half2*>(&u);
    return __half22float2(h);
}

// ---------------- per-node precompute: 4 nodes/warp, lane = channel ----------------
__global__ void __launch_bounds__(256) precompute_kernel(const float* __restrict__ feat,
                                                         const float* __restrict__ W,
                                                         int n_nodes) {
    __shared__ float Ws[5 * 1024];
    __shared__ float4 xs[8][NPW * 32];

    for (int i = threadIdx.x; i < 5 * 1024; i += blockDim.x) {
        int p = i >> 10;
        float s = (p == 0 || p == 3) ? ALPHA0 : ALPHA1;
        Ws[i] = s * W[i];
    }
    __syncthreads();

    int lane = threadIdx.x & 31;
    int wl   = threadIdx.x >> 5;
    int warp = (blockIdx.x * blockDim.x + threadIdx.x) >> 5;
    int nwarp = (gridDim.x * blockDim.x) >> 5;

    for (int nb = warp * NPW; nb < n_nodes; nb += nwarp * NPW) {
        #pragma unroll
        for (int nn = 0; nn < NPW; nn++) {
            int n = nb + nn;
            float4 v = make_float4(0.f, 0.f, 0.f, 0.f);
            if (n < n_nodes) {
                const float* x = feat + (size_t)n * 128;
                v.x = x[lane];
                v.y = x[32 + 3 * lane];
                v.z = x[33 + 3 * lane];
                v.w = x[34 + 3 * lane];
            }
            xs[wl][nn * 32 + lane] = v;
        }
        __syncwarp();

        float a1[NPW], a2[NPW], b3[NPW][3], b4[NPW][3], b5[NPW][3];
        #pragma unroll
        for (int nn = 0; nn < NPW; nn++) {
            a1[nn] = 0.f; a2[nn] = 0.f;
            #pragma unroll
            for (int k = 0; k < 3; k++) { b3[nn][k] = 0.f; b4[nn][k] = 0.f; b5[nn][k] = 0.f; }
        }

        #pragma unroll 4
        for (int u = 0; u < 32; u++) {
            float w0 = Ws[          u * 32 + lane];
            float w1 = Ws[1024 +    u * 32 + lane];
            float w2 = Ws[2048 +    u * 32 + lane];
            float w3 = Ws[3072 +    u * 32 + lane];
            float w4 = Ws[4096 +    u * 32 + lane];
            #pragma unroll
            for (int nn = 0; nn < NPW; nn++) {
                float4 v = xs[wl][nn * 32 + u];   // broadcast
                a1[nn] = fmaf(v.x, w0, a1[nn]);
                a2[nn] = fmaf(v.x, w1, a2[nn]);
                b3[nn][0] = fmaf(v.y, w2, b3[nn][0]);
                b3[nn][1] = fmaf(v.z, w2, b3[nn][1]);
                b3[nn][2] = fmaf(v.w, w2, b3[nn][2]);
                b4[nn][0] = fmaf(v.y, w3, b4[nn][0]);
                b4[nn][1] = fmaf(v.z, w3, b4[nn][1]);
                b4[nn][2] = fmaf(v.w, w3, b4[nn][2]);
                b5[nn][0] = fmaf(v.y, w4, b5[nn][0]);
                b5[nn][1] = fmaf(v.z, w4, b5[nn][1]);
                b5[nn][2] = fmaf(v.w, w4, b5[nn][2]);
            }
        }

        #pragma unroll
        for (int nn = 0; nn < NPW; nn++) {
            int n = nb + nn;
            if (n >= n_nodes) break;
            float c30 = b3[nn][0] * D0, c31 = b3[nn][1] * D1, c32 = b3[nn][2] * D0;
            float c40 = b4[nn][0] * E0, c41 = b4[nn][1] * E1, c42 = b4[nn][2] * E0;
            uint4 p;
            p.x = pack2(a1[nn], a2[nn]);
            p.y = pack2(c30, c31);
            p.z = pack2(c32, c40);
            p.w = pack2(c41, c42);
            uint2 q;
            q.x = pack2(b5[nn][0], b5[nn][1]);
            q.y = pack2(b5[nn][2], 0.f);
            g_node4[n * 32 + lane] = p;
            g_node2[n * 32 + lane] = q;
        }
        __syncwarp();
    }
}

// ---------------- dual-edge kernel: each half-warp owns one edge, lane owns 2 channels ----------------
__global__ void __launch_bounds__(256) edge_kernel(const float* __restrict__ sh,
                                                   const int* __restrict__ eidx,
                                                   float* __restrict__ out,
                                                   int n_edges) {
    // per-warp staging: 2 edges x 144 floats (pad 144 makes all STS conflict-free across halves)
    __shared__ __align__(16) float buf[8][2 * 144];
    const unsigned FULL = 0xFFFFFFFFu;
    int lane   = threadIdx.x & 31;
    int lane16 = lane & 15;
    int half   = lane >> 4;
    int wl     = threadIdx.x >> 5;
    int warp   = (blockIdx.x * blockDim.x + threadIdx.x) >> 5;
    int nwarp  = (gridDim.x * blockDim.x) >> 5;
    float* b = buf[wl] + half * 144;

    int e = warp * 2;            // n_edges is even; pairs stay complete
    int stride = nwarp * 2;

    int src_h = 0, dst_h = 0;
    float sv = 0.f;
    if (e < n_edges) {
        int tmp = 0;
        if (lane < 4) tmp = eidx[(lane >> 1) * n_edges + e + (lane & 1)];
        src_h = __shfl_sync(FULL, tmp, half);
        dst_h = __shfl_sync(FULL, tmp, 2 + half);
        sv = (lane16 < 9) ? sh[(size_t)(e + half) * 9 + lane16] : 0.f;
    }

    while (e < n_edges) {
        // record gather for both channels of this half's edge (issued first)
        uint4 rp0 = g_node4[src_h * 32 + lane16];
        uint4 rp1 = g_node4[src_h * 32 + 16 + lane16];
        uint2 rq0 = g_node2[src_h * 32 + lane16];
        uint2 rq1 = g_node2[src_h * 32 + 16 + lane16];

        // prefetch next pair's idx + sh while gather is in flight
        int en = e + stride;
        int nsrc = 0, ndst = 0;
        float nsv = 0.f;
        if (en < n_edges) {
            int tmp = 0;
            if (lane < 4) tmp = eidx[(lane >> 1) * n_edges + en + (lane & 1)];
            nsrc = __shfl_sync(FULL, tmp, half);
            ndst = __shfl_sync(FULL, tmp, 2 + half);
            nsv = (lane16 < 9) ? sh[(size_t)(en + half) * 9 + lane16] : 0.f;
        }

        // width-16 broadcasts: each half gets its own edge's sh
        float s0  = __shfl_sync(FULL, sv, 0, 16);
        float s1x = __shfl_sync(FULL, sv, 1, 16);
        float s1y = __shfl_sync(FULL, sv, 2, 16);
        float s1z = __shfl_sync(FULL, sv, 3, 16);
        float q0  = __shfl_sync(FULL, sv, 4, 16);
        float q1v = __shfl_sync(FULL, sv, 5, 16);
        float q2  = __shfl_sync(FULL, sv, 6, 16);
        float q3  = __shfl_sync(FULL, sv, 7, 16);
        float q4  = __shfl_sync(FULL, sv, 8, 16);

        float n2q2 = N2 * q2;
        float n1q4 = N1 * q4;
        float n1q0 = N1 * q0;
        float S00 = -(n2q2 + n1q4), S01 = N3 * q1v, S02 = n1q0;
        float S10 = N4 * q1v,       S11 = n2q2,     S12 = N4 * q3;
        float S20 = n1q0,           S21 = N3 * q3,  S22 = n1q4 - n2q2;
        float ds1x = D0 * s1x, ds1y = D1 * s1y, ds1z = D0 * s1z;

        #pragma unroll
        for (int c = 0; c < 2; c++) {
            uint4 rp = c ? rp1 : rp0;
            uint2 rq = c ? rq1 : rq0;
            int ch = lane16 + 16 * c;

            float2 u0 = unpack2(rp.x);   // a1, a2
            float2 u1 = unpack2(rp.y);   // b3x, b3y
            float2 u2 = unpack2(rp.z);   // b3z, b4x
            float2 u3 = unpack2(rp.w);   // b4y, b4z
            float2 u4 = unpack2(rq.x);   // b5x, b5y
            float2 u5 = unpack2(rq.y);   // b5z, -
            float a1 = u0.x, a2 = u0.y;
            float b3x = u1.x, b3y = u1.y, b3z = u2.x;
            float b4x = u2.y, b4y = u3.x, b4z = u3.y;
            float b5x = u4.x, b5y = u4.y, b5z = u5.x;

            float m0 = s0 * a1;
            m0 = fmaf(s1x, b4x, m0);
            m0 = fmaf(s1y, b4y, m0);
            m0 = fmaf(s1z, b4z, m0);

            float m1x = fmaf(ds1x, a2,
                        fmaf(s0, b3x,
                        fmaf(S00, b5x,
                        fmaf(S01, b5y, S02 * b5z))));
            float m1y = fmaf(ds1y, a2,
                        fmaf(s0, b3y,
                        fmaf(S10, b5x,
                        fmaf(S11, b5y, S12 * b5z))));
            float m1z = fmaf(ds1z, a2,
                        fmaf(s0, b3z,
                        fmaf(S20, b5x,
                        fmaf(S21, b5y, S22 * b5z))));

            b[ch]              = m0;
            b[32 + 3 * ch + 0] = m1x;
            b[32 + 3 * ch + 1] = m1y;
            b[32 + 3 * ch + 2] = m1z;
        }
        __syncwarp();

        // two vector-red rounds per half (64 floats each)
        float4 v0 = *reinterpret_cast<float4*>(b + 4 * lane16);
        float4 v1 = *reinterpret_cast<float4*>(b + 64 + 4 * lane16);
        float* dbase = out + (size_t)dst_h * 128 + 4 * lane16;
        asm volatile("red.global.add.v4.f32 [%0], {%1,%2,%3,%4};"
                     :: "l"(dbase), "f"(v0.x), "f"(v0.y), "f"(v0.z), "f"(v0.w) : "memory");
        asm volatile("red.global.add.v4.f32 [%0], {%1,%2,%3,%4};"
                     :: "l"(dbase + 64), "f"(v1.x), "f"(v1.y), "f"(v1.z), "f"(v1.w) : "memory");
        __syncwarp();

        e = en; src_h = nsrc; dst_h = ndst; sv = nsv;
    }
}

// ---------------- launch ----------------
extern "C" void kernel_launch(void* const* d_in, const int* in_sizes, int n_in,
                              void* d_out, int out_size) {
    const float* feat = (const float*)d_in[0];
    const float* sh   = (const float*)d_in[1];
    const int*   eidx = (const int*)d_in[2];
    const float* W    = (const float*)d_in[3];
    int n_nodes = in_sizes[0] / 128;
    int n_edges = in_sizes[2] / 2;

    cudaMemsetAsync(d_out, 0, (size_t)out_size * sizeof(float));

    int warps_needed = (n_nodes + NPW - 1) / NPW;
    int pre_blocks = (warps_needed + 7) / 8;
    precompute_kernel<<<pre_blocks, 256>>>(feat, W, n_nodes);

    edge_kernel<<<2048, 256>>>(sh, eidx, (float*)d_out, n_edges);
}